// round 1
// baseline (speedup 1.0000x reference)
#include <cuda_runtime.h>
#include <cstdint>

// Problem constants
#define NT   8192      // tokens
#define INF  4096      // in features
#define OUTF 4096      // out features
#define NNZC 1677722   // nnz

// Scratch (device globals: allocation-free rule)
__device__ float g_xT[(size_t)INF * NT];     // x transposed: [c][n]
__device__ float g_outT[(size_t)OUTF * NT];  // out transposed: [o][n]
__device__ int2  g_colw[NNZC];               // CSR payload: (col, weight-bits)
__device__ int   g_hist[OUTF];
__device__ int   g_rowstart[OUTF + 1];
__device__ int   g_cursor[OUTF];
__device__ int   g_is64;

// ---------------------------------------------------------------------------
// 0) Detect index dtype: int64 stores values < 4096 -> every odd 32-bit word 0
__global__ void k_detect(const int* __restrict__ idx32) {
    if (threadIdx.x == 0 && blockIdx.x == 0) {
        int z = 0;
        #pragma unroll
        for (int k = 1; k < 128; k += 2) z |= idx32[k];
        g_is64 = (z == 0) ? 1 : 0;
    }
}

// 1) Zero histogram
__global__ void k_zero_hist() {
    int i = blockIdx.x * blockDim.x + threadIdx.x;
    if (i < OUTF) g_hist[i] = 0;
}

__device__ __forceinline__ int load_idx(const void* idxv, long long pos) {
    if (g_is64) return (int)((const long long*)idxv)[pos];
    return ((const int*)idxv)[pos];
}

// 2) Histogram of output rows
__global__ void k_hist(const void* __restrict__ idxv, int nnz) {
    int j = blockIdx.x * blockDim.x + threadIdx.x;
    if (j >= nnz) return;
    int o = load_idx(idxv, j);
    atomicAdd(&g_hist[o], 1);
}

// 3) Exclusive scan of 4096 counts (single block, 1024 threads, 4/thread)
__global__ void k_scan() {
    __shared__ int s[1024];
    int t = threadIdx.x;
    int v[4]; int sum = 0;
    #pragma unroll
    for (int i = 0; i < 4; i++) { v[i] = g_hist[t * 4 + i]; sum += v[i]; }
    s[t] = sum;
    __syncthreads();
    for (int off = 1; off < 1024; off <<= 1) {
        int x = (t >= off) ? s[t - off] : 0;
        __syncthreads();
        s[t] += x;
        __syncthreads();
    }
    int excl = (t == 0) ? 0 : s[t - 1];
    #pragma unroll
    for (int i = 0; i < 4; i++) {
        int idx = t * 4 + i;
        g_rowstart[idx] = excl;
        g_cursor[idx]   = excl;
        excl += v[i];
    }
    if (t == 1023) g_rowstart[OUTF] = excl;
}

// 4) Scatter (col, weight) into CSR order by output row (dups kept -> summed)
__global__ void k_scatter(const void* __restrict__ idxv,
                          const float* __restrict__ w, int nnz) {
    int j = blockIdx.x * blockDim.x + threadIdx.x;
    if (j >= nnz) return;
    int o = load_idx(idxv, j);
    int c = load_idx(idxv, (long long)nnz + j);
    int p = atomicAdd(&g_cursor[o], 1);
    g_colw[p] = make_int2(c, __float_as_int(w[j]));
}

// 5) Transpose x [NT, INF] -> g_xT [INF, NT]
__global__ void k_transpose_x(const float* __restrict__ in) {
    __shared__ float tile[32][33];
    int x = blockIdx.x * 32 + threadIdx.x;  // c
    int y = blockIdx.y * 32 + threadIdx.y;  // n
    #pragma unroll
    for (int i = 0; i < 32; i += 8)
        tile[threadIdx.y + i][threadIdx.x] = in[(size_t)(y + i) * INF + x];
    __syncthreads();
    int xo = blockIdx.y * 32 + threadIdx.x;  // n
    int yo = blockIdx.x * 32 + threadIdx.y;  // c
    #pragma unroll
    for (int i = 0; i < 32; i += 8)
        g_xT[(size_t)(yo + i) * NT + xo] = tile[threadIdx.x][threadIdx.y + i];
}

// 6) SpMM: each warp covers 128 tokens (float4/lane) x 8 output rows.
//    Per nnz: uniform 8B CSR load + coalesced 512B/warp xT load + 4 FMA/lane.
__global__ void __launch_bounds__(256) k_spmm() {
    int warp = threadIdx.x >> 5;
    int lane = threadIdx.x & 31;
    int tcol = blockIdx.y * 128 + lane * 4;        // token column (float index)
    int o0   = blockIdx.x * 64 + warp * 8;

    #pragma unroll 1
    for (int r = 0; r < 8; ++r) {
        int o = o0 + r;
        int s = g_rowstart[o];
        int e = g_rowstart[o + 1];
        float4 acc = make_float4(0.f, 0.f, 0.f, 0.f);
        int j = s;
        for (; j + 4 <= e; j += 4) {
            int2 a = g_colw[j];
            int2 b = g_colw[j + 1];
            int2 c = g_colw[j + 2];
            int2 d = g_colw[j + 3];
            float4 xa = *(const float4*)&g_xT[((size_t)a.x << 13) + tcol];
            float4 xb = *(const float4*)&g_xT[((size_t)b.x << 13) + tcol];
            float4 xc = *(const float4*)&g_xT[((size_t)c.x << 13) + tcol];
            float4 xd = *(const float4*)&g_xT[((size_t)d.x << 13) + tcol];
            float wa = __int_as_float(a.y);
            float wb = __int_as_float(b.y);
            float wc = __int_as_float(c.y);
            float wd = __int_as_float(d.y);
            acc.x = fmaf(wa, xa.x, acc.x); acc.y = fmaf(wa, xa.y, acc.y);
            acc.z = fmaf(wa, xa.z, acc.z); acc.w = fmaf(wa, xa.w, acc.w);
            acc.x = fmaf(wb, xb.x, acc.x); acc.y = fmaf(wb, xb.y, acc.y);
            acc.z = fmaf(wb, xb.z, acc.z); acc.w = fmaf(wb, xb.w, acc.w);
            acc.x = fmaf(wc, xc.x, acc.x); acc.y = fmaf(wc, xc.y, acc.y);
            acc.z = fmaf(wc, xc.z, acc.z); acc.w = fmaf(wc, xc.w, acc.w);
            acc.x = fmaf(wd, xd.x, acc.x); acc.y = fmaf(wd, xd.y, acc.y);
            acc.z = fmaf(wd, xd.z, acc.z); acc.w = fmaf(wd, xd.w, acc.w);
        }
        for (; j < e; ++j) {
            int2 a = g_colw[j];
            float4 xa = *(const float4*)&g_xT[((size_t)a.x << 13) + tcol];
            float wa = __int_as_float(a.y);
            acc.x = fmaf(wa, xa.x, acc.x); acc.y = fmaf(wa, xa.y, acc.y);
            acc.z = fmaf(wa, xa.z, acc.z); acc.w = fmaf(wa, xa.w, acc.w);
        }
        *(float4*)&g_outT[((size_t)o << 13) + tcol] = acc;
    }
}

// 7) Transpose back + bias: out[n][o] = g_outT[o][n] + bias[o]
__global__ void k_out(const float* __restrict__ bias, float* __restrict__ out) {
    __shared__ float tile[32][33];
    int n = blockIdx.x * 32 + threadIdx.x;
    int o = blockIdx.y * 32 + threadIdx.y;
    #pragma unroll
    for (int i = 0; i < 32; i += 8)
        tile[threadIdx.y + i][threadIdx.x] = g_outT[(size_t)(o + i) * NT + n];
    __syncthreads();
    int oo = blockIdx.y * 32 + threadIdx.x;
    int nn = blockIdx.x * 32 + threadIdx.y;
    float b = bias[oo];
    #pragma unroll
    for (int i = 0; i < 32; i += 8)
        out[(size_t)(nn + i) * OUTF + oo] = tile[threadIdx.x][threadIdx.y + i] + b;
}

extern "C" void kernel_launch(void* const* d_in, const int* in_sizes, int n_in,
                              void* d_out, int out_size) {
    const float* x    = (const float*)d_in[0];  // [8192, 4096] f32
    const float* w    = (const float*)d_in[1];  // [NNZ] f32
    const float* bias = (const float*)d_in[2];  // [4096] f32
    const void*  idx  = d_in[3];                // [2, NNZ] int64 or int32
    float* out = (float*)d_out;                 // [8192, 4096] f32

    int nnz = in_sizes[1];                      // NNZ from weights count

    k_detect<<<1, 32>>>((const int*)idx);
    k_zero_hist<<<(OUTF + 255) / 256, 256>>>();
    k_hist<<<(nnz + 255) / 256, 256>>>(idx, nnz);
    k_scan<<<1, 1024>>>();
    k_scatter<<<(nnz + 255) / 256, 256>>>(idx, w, nnz);

    {
        dim3 b(32, 8);
        dim3 g(INF / 32, NT / 32);
        k_transpose_x<<<g, b>>>(x);
    }

    {
        dim3 g(OUTF / 64, NT / 128);  // x = o-blocks (fast) -> L2 shares xT tile
        k_spmm<<<g, 256>>>();
    }

    {
        dim3 b(32, 8);
        dim3 g(NT / 32, OUTF / 32);
        k_out<<<g, b>>>(bias, out);
    }
}

// round 3
// speedup vs baseline: 3.0842x; 3.0842x over previous
#include <cuda_runtime.h>
#include <cuda_fp16.h>
#include <cstdint>

// Problem constants
#define NTOK 8192
#define INF  4096
#define OUTF 4096

// GEMM tiling
#define MT    128                // M tile
#define NTLE  256                // N tile
#define KCH   32                 // K chunk (halves)
#define STAGES 4
#define NCH   (INF / KCH)        // 128 chunks
#define ROWPITCH 80              // bytes per smem row (32 halves + 8 pad) -> ldmatrix conflict-free
#define STG   ((MT + NTLE) * ROWPITCH)   // 30720 bytes per stage
#define SMEM_TOTAL (STAGES * STG)        // 122880

// Scratch (device globals: allocation-free rule)
__device__ float  g_wf[(size_t)OUTF * INF];   // densified W fp32 (atomicAdd target)
__device__ __half g_wh[(size_t)OUTF * INF];   // W fp16 [o][k]
__device__ __half g_xh[(size_t)NTOK * INF];   // x fp16 [m][k]
__device__ int    g_is64;

// ---------------------------------------------------------------------------
// PTX helpers (all base-sm_80-class: legal on plain sm_103 target)
__device__ __forceinline__ uint32_t s2u(const void* p) {
    uint32_t a;
    asm("{ .reg .u64 t; cvta.to.shared.u64 t, %1; cvt.u32.u64 %0, t; }"
        : "=r"(a) : "l"(p));
    return a;
}
#define CP_ASYNC16(smem, gptr) \
    asm volatile("cp.async.cg.shared.global [%0], [%1], 16;" :: "r"(smem), "l"(gptr))
#define CP_COMMIT() asm volatile("cp.async.commit_group;" ::: "memory")
#define CP_WAIT(n)  asm volatile("cp.async.wait_group %0;" :: "n"(n) : "memory")

__device__ __forceinline__ void ldsm4(uint32_t* r, uint32_t addr) {
    asm volatile("ldmatrix.sync.aligned.m8n8.x4.shared.b16 {%0,%1,%2,%3}, [%4];"
        : "=r"(r[0]), "=r"(r[1]), "=r"(r[2]), "=r"(r[3]) : "r"(addr));
}
__device__ __forceinline__ void mma16816(float* d, const uint32_t* a,
                                         uint32_t b0, uint32_t b1) {
    asm volatile(
        "mma.sync.aligned.m16n8k16.row.col.f32.f16.f16.f32 "
        "{%0,%1,%2,%3}, {%4,%5,%6,%7}, {%8,%9}, {%0,%1,%2,%3};"
        : "+f"(d[0]), "+f"(d[1]), "+f"(d[2]), "+f"(d[3])
        : "r"(a[0]), "r"(a[1]), "r"(a[2]), "r"(a[3]), "r"(b0), "r"(b1));
}

// ---------------------------------------------------------------------------
// Prep kernels
__global__ void k_detect(const int* __restrict__ idx32) {
    if (threadIdx.x == 0 && blockIdx.x == 0) {
        int z = 0;
        #pragma unroll
        for (int k = 1; k < 128; k += 2) z |= idx32[k];
        g_is64 = (z == 0) ? 1 : 0;
    }
}

__global__ void k_zero_wf() {
    size_t i = (size_t)blockIdx.x * blockDim.x + threadIdx.x;
    ((float4*)g_wf)[i] = make_float4(0.f, 0.f, 0.f, 0.f);
}

__device__ __forceinline__ int load_idx(const void* idxv, long long pos) {
    if (g_is64) return (int)((const long long*)idxv)[pos];
    return ((const int*)idxv)[pos];
}

__global__ void k_scatter(const void* __restrict__ idxv,
                          const float* __restrict__ w, int nnz) {
    int j = blockIdx.x * blockDim.x + threadIdx.x;
    if (j >= nnz) return;
    int o = load_idx(idxv, j);
    int c = load_idx(idxv, (long long)nnz + j);
    atomicAdd(&g_wf[(size_t)o * INF + c], w[j]);
}

__global__ void k_conv_w() {
    size_t i = (size_t)blockIdx.x * blockDim.x + threadIdx.x;  // one float4
    float4 f = ((const float4*)g_wf)[i];
    __half2 a = __floats2half2_rn(f.x, f.y);
    __half2 b = __floats2half2_rn(f.z, f.w);
    uint2 v;
    v.x = *(uint32_t*)&a;
    v.y = *(uint32_t*)&b;
    ((uint2*)g_wh)[i] = v;
}

__global__ void k_conv_x(const float* __restrict__ x) {
    size_t i = (size_t)blockIdx.x * blockDim.x + threadIdx.x;
    float4 f = ((const float4*)x)[i];
    __half2 a = __floats2half2_rn(f.x, f.y);
    __half2 b = __floats2half2_rn(f.z, f.w);
    uint2 v;
    v.x = *(uint32_t*)&a;
    v.y = *(uint32_t*)&b;
    ((uint2*)g_xh)[i] = v;
}

// ---------------------------------------------------------------------------
// GEMM: out[m][n] = sum_k xh[m][k] * wh[n][k] + bias[n]
// 512 threads = 16 warps (4 m-warps x 4 n-warps), warp tile 32x64.
// smem stage: rows 0..127 = A (m), rows 128..383 = B (n), pitch 80B.
__device__ __forceinline__ void load_stage(uint32_t sb, int s, int ch,
                                           int m0, int n0, int tid) {
    uint32_t stb = sb + s * STG;
    int kk = ch * KCH;
    #pragma unroll
    for (int i = 0; i < 3; i++) {
        int idx = tid + i * 512;          // 1536 x 16B chunks per stage
        int row = idx >> 2;
        int c   = idx & 3;
        uint32_t so = stb + row * ROWPITCH + c * 16;
        const __half* g;
        if (row < MT)
            g = &g_xh[(size_t)(m0 + row) * INF + kk + c * 8];
        else
            g = &g_wh[(size_t)(n0 + row - MT) * INF + kk + c * 8];
        CP_ASYNC16(so, g);
    }
}

__global__ void __launch_bounds__(512, 1) k_gemm(
    const float* __restrict__ bias, float* __restrict__ out)
{
    extern __shared__ char sm[];
    uint32_t sb = s2u(sm);
    int tid = threadIdx.x;
    int wid = tid >> 5, lane = tid & 31;
    int mw = wid >> 2, nw = wid & 3;      // 4x4 warp grid
    int m0 = blockIdx.y * MT;
    int n0 = blockIdx.x * NTLE;

    float acc[2][8][4];
    #pragma unroll
    for (int i = 0; i < 2; i++)
        #pragma unroll
        for (int j = 0; j < 8; j++)
            #pragma unroll
            for (int q = 0; q < 4; q++) acc[i][j][q] = 0.f;

    // per-thread ldmatrix base offsets (within a stage)
    uint32_t a_off = (uint32_t)(mw * 32 + (lane & 15)) * ROWPITCH + (lane >> 4) * 16;
    uint32_t b_off = (uint32_t)(MT + nw * 64 + (lane & 15)) * ROWPITCH + (lane >> 4) * 16;

    // prologue: stages 0..2
    #pragma unroll
    for (int s = 0; s < STAGES - 1; s++) {
        load_stage(sb, s, s, m0, n0, tid);
        CP_COMMIT();
    }

    #pragma unroll 1
    for (int ch = 0; ch < NCH; ch++) {
        CP_WAIT(STAGES - 2);
        __syncthreads();

        // issue loads for chunk ch+3 (into the stage consumed at ch-1)
        if (ch + STAGES - 1 < NCH)
            load_stage(sb, (ch + STAGES - 1) & (STAGES - 1), ch + STAGES - 1,
                       m0, n0, tid);
        CP_COMMIT();

        uint32_t stb = sb + (ch & (STAGES - 1)) * STG;
        uint32_t ab = stb + a_off;
        uint32_t bb = stb + b_off;
        #pragma unroll
        for (int ks = 0; ks < 2; ks++) {
            uint32_t a0[4], a1[4];
            ldsm4(a0, ab + ks * 32);
            ldsm4(a1, ab + 16 * ROWPITCH + ks * 32);
            #pragma unroll
            for (int j = 0; j < 4; j++) {
                uint32_t b[4];
                ldsm4(b, bb + j * 16 * ROWPITCH + ks * 32);
                mma16816(acc[0][2 * j],     a0, b[0], b[2]);
                mma16816(acc[0][2 * j + 1], a0, b[1], b[3]);
                mma16816(acc[1][2 * j],     a1, b[0], b[2]);
                mma16816(acc[1][2 * j + 1], a1, b[1], b[3]);
            }
        }
    }

    // epilogue: add bias, store float2 pairs
    int l4 = lane >> 2;            // row 0..7 within 8
    int l2 = (lane & 3) * 2;       // col pair base
    #pragma unroll
    for (int im = 0; im < 2; im++) {
        int mbase = m0 + mw * 32 + im * 16 + l4;
        #pragma unroll
        for (int jn = 0; jn < 8; jn++) {
            int col = n0 + nw * 64 + jn * 8 + l2;
            float2 bv = *(const float2*)(bias + col);
            float2 v0, v1;
            v0.x = acc[im][jn][0] + bv.x;
            v0.y = acc[im][jn][1] + bv.y;
            v1.x = acc[im][jn][2] + bv.x;
            v1.y = acc[im][jn][3] + bv.y;
            *(float2*)(out + (size_t)mbase * OUTF + col) = v0;
            *(float2*)(out + (size_t)(mbase + 8) * OUTF + col) = v1;
        }
    }
}

// ---------------------------------------------------------------------------
extern "C" void kernel_launch(void* const* d_in, const int* in_sizes, int n_in,
                              void* d_out, int out_size) {
    const float* x    = (const float*)d_in[0];  // [8192, 4096] f32
    const float* w    = (const float*)d_in[1];  // [NNZ] f32
    const float* bias = (const float*)d_in[2];  // [4096] f32
    const void*  idx  = d_in[3];                // [2, NNZ] int64 or int32
    float* out = (float*)d_out;                 // [8192, 4096] f32
    int nnz = in_sizes[1];

    static bool attr_set = false;
    if (!attr_set) {
        cudaFuncSetAttribute(k_gemm, cudaFuncAttributeMaxDynamicSharedMemorySize,
                             SMEM_TOTAL);
        attr_set = true;
    }

    k_detect<<<1, 32>>>((const int*)idx);
    k_zero_wf<<<(int)((size_t)OUTF * INF / 4 / 256), 256>>>();
    k_scatter<<<(nnz + 255) / 256, 256>>>(idx, w, nnz);
    k_conv_w<<<(int)((size_t)OUTF * INF / 4 / 256), 256>>>();
    k_conv_x<<<(int)((size_t)NTOK * INF / 4 / 256), 256>>>(x);

    dim3 grid(OUTF / NTLE, NTOK / MT);   // (16, 64)
    k_gemm<<<grid, 512, SMEM_TOTAL>>>(bias, out);
}